// round 3
// baseline (speedup 1.0000x reference)
#include <cuda_runtime.h>
#include <cstdint>

#define N_MAX 100000
#define E_MAX 1600000
#define NB_SCAN 128

// ---------------- scratch (static device memory; no allocation) ----------------
__device__ int   g_deg_out[N_MAX];
__device__ int   g_deg_in[N_MAX];
__device__ float g_norm_src[N_MAX];
__device__ float g_norm_dst[N_MAX];
__device__ int   g_row_ptr[N_MAX + 1];
__device__ int   g_fill[N_MAX];
__device__ int   g_col[E_MAX];
__device__ float g_t[N_MAX * 64];   // per-layer transformed features (norm_src * h @ W)
__device__ float g_h[N_MAX * 64];   // per-layer output features
__device__ int g_bsum[NB_SCAN];
__device__ int g_boff[NB_SCAN];

// ---------------- threefry-2x32 (exact JAX algorithm) ----------------
__device__ __forceinline__ void d_threefry(uint32_t k0, uint32_t k1,
                                           uint32_t x0, uint32_t x1,
                                           uint32_t& y0, uint32_t& y1) {
    uint32_t k2 = k0 ^ k1 ^ 0x1BD11BDAu;
    x0 += k0; x1 += k1;
#define TFR(r) { x0 += x1; x1 = __funnelshift_l(x1, x1, r); x1 ^= x0; }
    TFR(13) TFR(15) TFR(26) TFR(6)
    x0 += k1; x1 += k2 + 1u;
    TFR(17) TFR(29) TFR(16) TFR(24)
    x0 += k2; x1 += k0 + 2u;
    TFR(13) TFR(15) TFR(26) TFR(6)
    x0 += k0; x1 += k1 + 3u;
    TFR(17) TFR(29) TFR(16) TFR(24)
    x0 += k1; x1 += k2 + 4u;
    TFR(13) TFR(15) TFR(26) TFR(6)
    x0 += k2; x1 += k0 + 5u;
#undef TFR
    y0 = x0; y1 = x1;
}

static inline uint32_t h_rotl(uint32_t x, int r) { return (x << r) | (x >> (32 - r)); }
static void h_threefry(uint32_t k0, uint32_t k1, uint32_t x0, uint32_t x1,
                       uint32_t& y0, uint32_t& y1) {
    uint32_t k2 = k0 ^ k1 ^ 0x1BD11BDAu;
    x0 += k0; x1 += k1;
#define TFR(r) { x0 += x1; x1 = h_rotl(x1, r); x1 ^= x0; }
    TFR(13) TFR(15) TFR(26) TFR(6)
    x0 += k1; x1 += k2 + 1u;
    TFR(17) TFR(29) TFR(16) TFR(24)
    x0 += k2; x1 += k0 + 2u;
    TFR(13) TFR(15) TFR(26) TFR(6)
    x0 += k0; x1 += k1 + 3u;
    TFR(17) TFR(29) TFR(16) TFR(24)
    x0 += k1; x1 += k2 + 4u;
    TFR(13) TFR(15) TFR(26) TFR(6)
    x0 += k2; x1 += k0 + 5u;
#undef TFR
    y0 = x0; y1 = x1;
}

// ---------------- graph prep kernels ----------------
__global__ void k_zero(int n) {
    int i = blockIdx.x * blockDim.x + threadIdx.x;
    if (i < n) { g_deg_out[i] = 0; g_deg_in[i] = 0; }
}

__global__ void k_degree(const int* __restrict__ src, const int* __restrict__ dst, int e) {
    int i = blockIdx.x * blockDim.x + threadIdx.x;
    if (i < e) {
        atomicAdd(&g_deg_out[src[i]], 1);
        atomicAdd(&g_deg_in[dst[i]], 1);
    }
}

__global__ void k_norm(int n) {
    int i = blockIdx.x * blockDim.x + threadIdx.x;
    if (i < n) {
        int a = g_deg_out[i];
        g_norm_src[i] = (a > 0) ? rsqrtf((float)a) : 0.f;
        int b = g_deg_in[i];
        g_norm_dst[i] = (b > 0) ? rsqrtf((float)b) : 0.f;
    }
}

__global__ void k_scan_reduce(int n) {
    __shared__ int s[1024];
    int t = threadIdx.x, i = blockIdx.x * 1024 + t;
    s[t] = (i < n) ? g_deg_in[i] : 0;
    __syncthreads();
    for (int off = 512; off > 0; off >>= 1) {
        if (t < off) s[t] += s[t + off];
        __syncthreads();
    }
    if (t == 0) g_bsum[blockIdx.x] = s[0];
}

__global__ void k_scan_bsum(int nb) {
    __shared__ int s[NB_SCAN];
    int t = threadIdx.x;
    int v = (t < nb) ? g_bsum[t] : 0;
    s[t] = v;
    __syncthreads();
    for (int off = 1; off < NB_SCAN; off <<= 1) {
        int a = (t >= off) ? s[t - off] : 0;
        __syncthreads();
        s[t] += a;
        __syncthreads();
    }
    if (t < nb) g_boff[t] = s[t] - v;
}

__global__ void k_scan_write(int n, int e) {
    __shared__ int s[1024];
    int t = threadIdx.x, i = blockIdx.x * 1024 + t;
    int v = (i < n) ? g_deg_in[i] : 0;
    s[t] = v;
    __syncthreads();
    for (int off = 1; off < 1024; off <<= 1) {
        int a = (t >= off) ? s[t - off] : 0;
        __syncthreads();
        s[t] += a;
        __syncthreads();
    }
    int excl = s[t] - v + g_boff[blockIdx.x];
    if (i < n) { g_row_ptr[i] = excl; g_fill[i] = excl; }
    if (i == 0) g_row_ptr[n] = e;
}

__global__ void k_csr(const int* __restrict__ src, const int* __restrict__ dst, int e) {
    int i = blockIdx.x * blockDim.x + threadIdx.x;
    if (i < e) {
        int p = atomicAdd(&g_fill[dst[i]], 1);
        g_col[p] = src[i];
    }
}

// ---------------- packed f32x2 helpers ----------------
__device__ __forceinline__ unsigned long long pk2(float x, float y) {
    unsigned long long r;
    asm("mov.b64 %0, {%1,%2};" : "=l"(r) : "f"(x), "f"(y));
    return r;
}
__device__ __forceinline__ void fma2(unsigned long long& d, unsigned long long a, unsigned long long b) {
    asm("fma.rn.f32x2 %0, %1, %2, %0;" : "+l"(d) : "l"(a), "l"(b));
}
__device__ __forceinline__ float2 upk2(unsigned long long v) {
    float2 r;
    asm("mov.b64 {%0,%1}, %2;" : "=f"(r.x), "=f"(r.y) : "l"(v));
    return r;
}

// ---------------- GEMM: T[r][:] = norm_src[r] * (H[r][:] @ W)  (64x64 W) ----------------
// block = 128 threads, 64 rows/block. Thread: 4 rows (rid+16i) x 4 col-pairs (cid+8j).
template <int EXT>
__global__ void __launch_bounds__(128) k_gemm64(const float* __restrict__ Hext,
                                                const float* __restrict__ W, int n) {
    __shared__ unsigned long long sW[64 * 32]; // [k][cpair] : (W[k][2c], W[k][2c+1])
    __shared__ float sH[64 * 65];              // [r][k], pad to 65 to break bank conflicts
    const float* H = EXT ? Hext : g_h;
    int tid = threadIdx.x;
    int rowBase = blockIdx.x * 64;

    // stage W: 2048 float2
    const float2* Wv = (const float2*)W;
    for (int idx = tid; idx < 2048; idx += 128) {
        float2 w = Wv[idx];
        sW[idx] = pk2(w.x, w.y);
    }
    // stage H tile: 64 rows x 64 cols, via float4
    for (int idx = tid; idx < 1024; idx += 128) {
        int r = idx >> 4;
        int f = idx & 15;
        int gr = rowBase + r;
        float4 v = make_float4(0.f, 0.f, 0.f, 0.f);
        if (gr < n) v = ((const float4*)H)[gr * 16 + f];
        float* p = &sH[r * 65 + f * 4];
        p[0] = v.x; p[1] = v.y; p[2] = v.z; p[3] = v.w;
    }
    __syncthreads();

    int cid = tid & 7;
    int rid = tid >> 3;
    unsigned long long acc[4][4];
#pragma unroll
    for (int i = 0; i < 4; i++)
#pragma unroll
        for (int j = 0; j < 4; j++) acc[i][j] = 0ull;

#pragma unroll 8
    for (int k = 0; k < 64; k++) {
        unsigned long long a[4], b[4];
#pragma unroll
        for (int i = 0; i < 4; i++) {
            float h = sH[(rid + 16 * i) * 65 + k];
            a[i] = pk2(h, h);
        }
#pragma unroll
        for (int j = 0; j < 4; j++) b[j] = sW[k * 32 + cid + 8 * j];
#pragma unroll
        for (int i = 0; i < 4; i++)
#pragma unroll
            for (int j = 0; j < 4; j++) fma2(acc[i][j], a[i], b[j]);
    }

#pragma unroll
    for (int i = 0; i < 4; i++) {
        int r = rowBase + rid + 16 * i;
        if (r < n) {
            float ns = g_norm_src[r];
#pragma unroll
            for (int j = 0; j < 4; j++) {
                float2 v = upk2(acc[i][j]);
                int c = cid + 8 * j;
                ((float2*)(g_t + r * 64))[c] = make_float2(v.x * ns, v.y * ns);
            }
        }
    }
}

// ---------------- aggregation: out[v] = f(sum_{u in N(v)} t[u]) ----------------
// one warp per node; lane handles 2 columns (float2)
// Dropout mask (partitionable threefry): for flat element index idx,
//   (y0,y1) = threefry(key, hi=0, lo=idx);  bits = y0 ^ y1;  keep <=> MSB(bits)==0
template <int LAYER>  // 0/1: relu+dropout -> g_h ; 2: plain -> d_out
__global__ void __launch_bounds__(256) k_agg(const float* __restrict__ bias,
                                             float* __restrict__ outp,
                                             uint32_t key0, uint32_t key1, int n) {
    int gw = (blockIdx.x * blockDim.x + threadIdx.x) >> 5;
    int lane = threadIdx.x & 31;
    if (gw >= n) return;

    // compute dropout keep-bits up front (hidden under the gather loop's latency)
    bool keep0 = true, keep1 = true;
    if (LAYER != 2) {
        uint32_t idx = (uint32_t)gw * 64u + 2u * (uint32_t)lane;
        uint32_t y0, y1;
        d_threefry(key0, key1, 0u, idx, y0, y1);
        keep0 = (((y0 ^ y1) >> 31) == 0u);
        d_threefry(key0, key1, 0u, idx + 1u, y0, y1);
        keep1 = (((y0 ^ y1) >> 31) == 0u);
    }

    int s = g_row_ptr[gw], e = g_row_ptr[gw + 1];
    const float2* T2 = (const float2*)g_t;
    float ax = 0.f, ay = 0.f;
    int i = s;
    for (; i + 4 <= e; i += 4) {
        int u0 = g_col[i], u1 = g_col[i + 1], u2 = g_col[i + 2], u3 = g_col[i + 3];
        float2 v0 = T2[u0 * 32 + lane];
        float2 v1 = T2[u1 * 32 + lane];
        float2 v2 = T2[u2 * 32 + lane];
        float2 v3 = T2[u3 * 32 + lane];
        ax += (v0.x + v1.x) + (v2.x + v3.x);
        ay += (v0.y + v1.y) + (v2.y + v3.y);
    }
    for (; i < e; i++) {
        int u = g_col[i];
        float2 v = T2[u * 32 + lane];
        ax += v.x; ay += v.y;
    }
    float nd = g_norm_dst[gw];
    float2 bb = ((const float2*)bias)[lane];
    float ox = ax * nd + bb.x;
    float oy = ay * nd + bb.y;
    if (LAYER != 2) {
        ox = fmaxf(ox, 0.f);
        oy = fmaxf(oy, 0.f);
        ox = keep0 ? ox * 2.f : 0.f;
        oy = keep1 ? oy * 2.f : 0.f;
    }
    float* out = (LAYER == 2) ? outp : g_h;
    ((float2*)out)[gw * 32 + lane] = make_float2(ox, oy);
}

// ---------------- launch ----------------
extern "C" void kernel_launch(void* const* d_in, const int* in_sizes, int n_in,
                              void* d_out, int out_size) {
    const float* x  = (const float*)d_in[0];
    const float* W0 = (const float*)d_in[1];
    const float* b0 = (const float*)d_in[2];
    const float* W1 = (const float*)d_in[3];
    const float* b1 = (const float*)d_in[4];
    const float* W2 = (const float*)d_in[5];
    const float* b2 = (const float*)d_in[6];
    const int*   src = (const int*)d_in[7];
    const int*   dst = (const int*)d_in[8];
    int n = in_sizes[0] / 64;
    int e = in_sizes[7];
    float* out = (float*)d_out;

    int nb = (n + 1023) / 1024;

    // graph structure
    k_zero<<<(n + 255) / 256, 256>>>(n);
    k_degree<<<(e + 255) / 256, 256>>>(src, dst, e);
    k_norm<<<(n + 255) / 256, 256>>>(n);
    k_scan_reduce<<<nb, 1024>>>(n);
    k_scan_bsum<<<1, NB_SCAN>>>(nb);
    k_scan_write<<<nb, 1024>>>(n, e);
    k_csr<<<(e + 255) / 256, 256>>>(src, dst, e);

    // dropout keys: base key(1) = (0,1); fold_in(key,l) = threefry(key=(0,1), msg=(0,l))
    uint32_t d0k0, d0k1, d1k0, d1k1;
    h_threefry(0u, 1u, 0u, 0u, d0k0, d0k1);
    h_threefry(0u, 1u, 0u, 1u, d1k0, d1k1);

    int gB = (n + 63) / 64;
    int aB = (n * 32 + 255) / 256;

    // layer 0
    k_gemm64<1><<<gB, 128>>>(x, W0, n);
    k_agg<0><<<aB, 256>>>(b0, nullptr, d0k0, d0k1, n);
    // layer 1
    k_gemm64<0><<<gB, 128>>>(nullptr, W1, n);
    k_agg<1><<<aB, 256>>>(b1, nullptr, d1k0, d1k1, n);
    // layer 2
    k_gemm64<0><<<gB, 128>>>(nullptr, W2, n);
    k_agg<2><<<aB, 256>>>(b2, out, 0u, 0u, n);
}